// round 2
// baseline (speedup 1.0000x reference)
#include <cuda_runtime.h>
#include <math.h>

// ---------------- problem constants ----------------
#define BB      16384
#define MEMD    128
#define TIMED   100
#define CONCATD 484          // 128+128+128+100
#define MAXNODES 1100000

// ---------------- device scratch (allocation-free rule: __device__ globals) ----
__device__ float g_G[BB * CONCATD];        // gathered concat input [B,484]
__device__ float g_time[BB * TIMED];       // time embedding [B,100]
__device__ float g_Wi1p[CONCATD * MEMD];   // row-permuted Wi1
__device__ float g_bufA_u[BB * MEMD];
__device__ float g_bufA_i[BB * MEMD];
__device__ float g_bufB_u[BB * MEMD];
__device__ float g_bufB_i[BB * MEMD];
__device__ float g_ut[BB * MEMD];          // user_t
__device__ float g_it[BB * MEMD];          // item_t
__device__ int   g_win[MAXNODES];          // scatter winner index

// ---------------- kernels ----------------

// Permute Wi1 rows: item_in = [dst,src,edge,time] == user_in with blocks 0/1 swapped.
__global__ void permute_Wi1_kernel(const float* __restrict__ Wi1)
{
    int k = blockIdx.x;      // 0..483
    int j = threadIdx.x;     // 0..127
    int ksrc;
    if (k < 128)       ksrc = k + 128;
    else if (k < 256)  ksrc = k - 128;
    else               ksrc = k;
    g_Wi1p[k * MEMD + j] = Wi1[ksrc * MEMD + j];
}

// Build [src_mem | dst_mem | edge | time_emb] and the standalone time buffer.
__global__ void gather_kernel(const int* __restrict__ src, const int* __restrict__ dst,
                              const float* __restrict__ mem, const float* __restrict__ edge,
                              const float* __restrict__ ts, const float* __restrict__ tw,
                              const float* __restrict__ tb)
{
    int r = blockIdx.x;      // row
    int j = threadIdx.x;     // 0..127
    int s = src[r], d = dst[r];
    float* Gr = g_G + (long)r * CONCATD;
    Gr[j]        = mem[(long)s * MEMD + j];
    Gr[128 + j]  = mem[(long)d * MEMD + j];
    Gr[256 + j]  = edge[(long)r * MEMD + j];
    if (j < TIMED) {
        float te = cosf(ts[r] * tw[j] + tb[j]);
        Gr[384 + j] = te;
        g_time[r * TIMED + j] = te;
    }
}

// Generic fp32 GEMM: C[M,128] = act(A @ W + bias), A given as up to 2 row-major
// segments (widths w0,w1; tight leading dims). BM=128, BN=128, BK=16, 256 thr,
// 8x8 register tile per thread.
__global__ __launch_bounds__(256)
void gemm128_kernel(const float* __restrict__ A0, int w0,
                    const float* __restrict__ A1, int w1,
                    int K,
                    const float* __restrict__ W, const float* __restrict__ bias,
                    float* __restrict__ C, int relu)
{
    __shared__ float As[16][132];   // padded to dodge bank conflicts on transposed store
    __shared__ float Bs[16][128];

    const int tid  = threadIdx.x;
    const int brow = blockIdx.x * 128;
    const int ty   = tid >> 4;      // 0..15
    const int tx   = tid & 15;      // 0..15

    float acc[8][8];
    #pragma unroll
    for (int i = 0; i < 8; i++)
        #pragma unroll
        for (int j = 0; j < 8; j++) acc[i][j] = 0.f;

    for (int kb = 0; kb < K; kb += 16) {
        // --- load A tile (128 rows x 16 k), store transposed As[k][m] ---
        #pragma unroll
        for (int l = 0; l < 8; l++) {
            int idx = tid + l * 256;        // 0..2047
            int m = idx >> 4;
            int k = idx & 15;
            int gk = kb + k;
            float v = 0.f;
            if (gk < K) {
                int row = brow + m;
                if (gk < w0) v = A0[(long)row * w0 + gk];
                else         v = A1[(long)row * w1 + (gk - w0)];
            }
            As[k][m] = v;
        }
        // --- load W tile (16 k x 128 n), coalesced ---
        #pragma unroll
        for (int l = 0; l < 8; l++) {
            int idx = tid + l * 256;
            int k = idx >> 7;
            int n = idx & 127;
            int gk = kb + k;
            Bs[k][n] = (gk < K) ? W[gk * 128 + n] : 0.f;
        }
        __syncthreads();

        #pragma unroll
        for (int kk = 0; kk < 16; kk++) {
            float a[8], b[8];
            #pragma unroll
            for (int i = 0; i < 8; i++) a[i] = As[kk][ty * 8 + i];
            #pragma unroll
            for (int j = 0; j < 8; j++) b[j] = Bs[kk][tx * 8 + j];
            #pragma unroll
            for (int i = 0; i < 8; i++)
                #pragma unroll
                for (int j = 0; j < 8; j++)
                    acc[i][j] = fmaf(a[i], b[j], acc[i][j]);
        }
        __syncthreads();
    }

    // epilogue: bias + optional relu
    #pragma unroll
    for (int i = 0; i < 8; i++) {
        int row = brow + ty * 8 + i;
        #pragma unroll
        for (int j = 0; j < 8; j++) {
            int col = tx * 8 + j;
            float v = acc[i][j] + bias[col];
            if (relu) v = fmaxf(v, 0.f);
            C[(long)row * 128 + col] = v;
        }
    }
}

// Scatter: emulate .at[src].set(user_t).at[dst].set(item_t) with deterministic
// "later wins" semantics (dst encoded as i+B so it always beats src).
__global__ void win_init_kernel(int nodes)
{
    int i = blockIdx.x * blockDim.x + threadIdx.x;
    if (i < nodes) g_win[i] = -1;
}

__global__ void win_mark_kernel(const int* __restrict__ src, const int* __restrict__ dst, int Bn)
{
    int i = blockIdx.x * blockDim.x + threadIdx.x;
    if (i < 2 * Bn) {
        int id = (i < Bn) ? src[i] : dst[i - Bn];
        atomicMax(&g_win[id], i);
    }
}

__global__ void scatter_write_kernel(const int* __restrict__ src, const int* __restrict__ dst,
                                     float* __restrict__ out_mem, int Bn)
{
    int i = blockIdx.x;   // 0..2B-1
    int j = threadIdx.x;  // 0..127
    int id;
    const float* row;
    if (i < Bn) { id = src[i];      row = g_ut + (long)i * MEMD; }
    else        { id = dst[i - Bn]; row = g_it + (long)(i - Bn) * MEMD; }
    if (g_win[id] == i)
        out_mem[(long)id * MEMD + j] = row[j];
}

// ---------------- launch ----------------
extern "C" void kernel_launch(void* const* d_in, const int* in_sizes, int n_in,
                              void* d_out, int out_size)
{
    const float* src_emb = (const float*)d_in[0];
    const float* dst_emb = (const float*)d_in[1];
    const int*   src_ids = (const int*)  d_in[2];
    const int*   dst_ids = (const int*)  d_in[3];
    const float* edge    = (const float*)d_in[4];
    const float* ts      = (const float*)d_in[5];
    const float* memory  = (const float*)d_in[6];
    const float* tw      = (const float*)d_in[7];
    const float* tb      = (const float*)d_in[8];
    const float* Wu1 = (const float*)d_in[9];   const float* bu1 = (const float*)d_in[10];
    const float* Wu2 = (const float*)d_in[11];  const float* bu2 = (const float*)d_in[12];
    const float* Wi1 = (const float*)d_in[13];  const float* bi1 = (const float*)d_in[14];
    const float* Wi2 = (const float*)d_in[15];  const float* bi2 = (const float*)d_in[16];
    const float* Wp1 = (const float*)d_in[17];  const float* bp1 = (const float*)d_in[18];
    const float* Wp2 = (const float*)d_in[19];  const float* bp2 = (const float*)d_in[20];
    const float* Wt1 = (const float*)d_in[21];  const float* bt1 = (const float*)d_in[22];
    const float* Wo  = (const float*)d_in[23];  const float* bo  = (const float*)d_in[24];

    const int Bn    = in_sizes[5];                 // timestamps: [B]
    const int nodes = in_sizes[6] / MEMD;          // memory: [N, 128]
    float* out = (float*)d_out;

    // resolve device-global scratch addresses
    float *dG, *dTime, *dWi1p, *dAu, *dAi, *dBu, *dBi, *dUt, *dIt;
    cudaGetSymbolAddress((void**)&dG,     g_G);
    cudaGetSymbolAddress((void**)&dTime,  g_time);
    cudaGetSymbolAddress((void**)&dWi1p,  g_Wi1p);
    cudaGetSymbolAddress((void**)&dAu,    g_bufA_u);
    cudaGetSymbolAddress((void**)&dAi,    g_bufA_i);
    cudaGetSymbolAddress((void**)&dBu,    g_bufB_u);
    cudaGetSymbolAddress((void**)&dBi,    g_bufB_i);
    cudaGetSymbolAddress((void**)&dUt,    g_ut);
    cudaGetSymbolAddress((void**)&dIt,    g_it);

    const int gemmGrid = Bn / 128;

    // 0) permute Wi1 rows (swap first two 128-blocks)
    permute_Wi1_kernel<<<CONCATD, MEMD>>>(Wi1);

    // 1) gather memory rows + time encoding -> g_G, g_time
    gather_kernel<<<Bn, MEMD>>>(src_ids, dst_ids, memory, edge, ts, tw, tb);

    // 2) branch-1 MLPs, layer 1: K=484, relu
    gemm128_kernel<<<gemmGrid, 256>>>(dG, CONCATD, dG, CONCATD, CONCATD, Wu1,   bu1, dAu, 1);
    gemm128_kernel<<<gemmGrid, 256>>>(dG, CONCATD, dG, CONCATD, CONCATD, dWi1p, bi1, dAi, 1);
    // layer 2: K=128, no relu
    gemm128_kernel<<<gemmGrid, 256>>>(dAu, MEMD, dAu, MEMD, MEMD, Wu2, bu2, dBu, 0);
    gemm128_kernel<<<gemmGrid, 256>>>(dAi, MEMD, dAi, MEMD, MEMD, Wi2, bi2, dBi, 0);

    // 3) shared projection MLP: relu layer then linear layer
    gemm128_kernel<<<gemmGrid, 256>>>(dBu, MEMD, dBu, MEMD, MEMD, Wp1, bp1, dAu, 1);
    gemm128_kernel<<<gemmGrid, 256>>>(dBi, MEMD, dBi, MEMD, MEMD, Wp1, bp1, dAi, 1);
    gemm128_kernel<<<gemmGrid, 256>>>(dAu, MEMD, dAu, MEMD, MEMD, Wp2, bp2, dBu, 0);
    gemm128_kernel<<<gemmGrid, 256>>>(dAi, MEMD, dAi, MEMD, MEMD, Wp2, bp2, dBi, 0);

    // 4) t-batch projection: [proj, time] (K=228), relu
    gemm128_kernel<<<gemmGrid, 256>>>(dBu, MEMD, dTime, TIMED, MEMD + TIMED, Wt1, bt1, dUt, 1);
    gemm128_kernel<<<gemmGrid, 256>>>(dBi, MEMD, dTime, TIMED, MEMD + TIMED, Wt1, bt1, dIt, 1);

    // 5) output projection: [t, embedding] (K=256) -> d_out rows [0,B) and [B,2B)
    gemm128_kernel<<<gemmGrid, 256>>>(dUt, MEMD, src_emb, MEMD, 2 * MEMD, Wo, bo, out, 0);
    gemm128_kernel<<<gemmGrid, 256>>>(dIt, MEMD, dst_emb, MEMD, 2 * MEMD, Wo, bo,
                                      out + (long)Bn * MEMD, 0);

    // 6) new_memory: copy the bank then scatter with deterministic last-wins
    long outHead = (long)2 * Bn * MEMD;
    if ((long)out_size >= outHead + (long)nodes * MEMD) {
        float* out_mem = out + outHead;
        cudaMemcpyAsync(out_mem, memory, (size_t)nodes * MEMD * sizeof(float),
                        cudaMemcpyDeviceToDevice);
        win_init_kernel<<<(nodes + 255) / 256, 256>>>(nodes);
        win_mark_kernel<<<(2 * Bn + 255) / 256, 256>>>(src_ids, dst_ids, Bn);
        scatter_write_kernel<<<2 * Bn, MEMD>>>(src_ids, dst_ids, out_mem, Bn);
    }
}

// round 4
// speedup vs baseline: 1.1197x; 1.1197x over previous
#include <cuda_runtime.h>
#include <cuda_bf16.h>
#include <math.h>
#include <stdint.h>

// ---------------- problem constants ----------------
#define BB       16384
#define MEMD     128
#define TIMED    100
#define CONCATD  484
#define MAXNODES 1100000

// weight offsets in transposed bf16 weight pool (each [128, K] K-major)
#define OFF_WU1  0                       // K=484
#define OFF_WI1  (484*128)               // K=484 (row-permuted)
#define OFF_WU2  (2*484*128)             // K=128
#define OFF_WI2  (OFF_WU2 + 128*128)
#define OFF_WP1  (OFF_WI2 + 128*128)
#define OFF_WP2  (OFF_WP1 + 128*128)
#define OFF_WT1  (OFF_WP2 + 128*128)     // K=228
#define OFF_WO   (OFF_WT1 + 228*128)     // K=256
#define WPOOL    (OFF_WO + 256*128)

#define SMS 72   // smem row stride in bf16 (padded, conflict-free ldmatrix)

// ---------------- device scratch ----------------
__device__ __nv_bfloat16 g_Gh[BB * CONCATD];
__device__ __nv_bfloat16 g_Gl[BB * CONCATD];
__device__ __nv_bfloat16 g_th[BB * TIMED];
__device__ __nv_bfloat16 g_tl[BB * TIMED];
__device__ __nv_bfloat16 g_seh[BB * MEMD], g_sel[BB * MEMD];
__device__ __nv_bfloat16 g_deh[BB * MEMD], g_del[BB * MEMD];
__device__ __nv_bfloat16 g_auh[BB * MEMD], g_aul[BB * MEMD];
__device__ __nv_bfloat16 g_aih[BB * MEMD], g_ail[BB * MEMD];
__device__ __nv_bfloat16 g_buh[BB * MEMD], g_bul[BB * MEMD];
__device__ __nv_bfloat16 g_bih[BB * MEMD], g_bil[BB * MEMD];
__device__ float         g_ut[BB * MEMD], g_it[BB * MEMD];
__device__ __nv_bfloat16 g_uth[BB * MEMD], g_utl[BB * MEMD];
__device__ __nv_bfloat16 g_ith[BB * MEMD], g_itl[BB * MEMD];
__device__ __nv_bfloat16 g_wth[WPOOL], g_wtl[WPOOL];
__device__ int g_win[MAXNODES];

// ---------------- helpers ----------------
__device__ __forceinline__ uint32_t smem_u32(const void* p) {
    uint32_t a;
    asm("{ .reg .u64 t; cvta.to.shared.u64 t, %1; cvt.u32.u64 %0, t; }" : "=r"(a) : "l"(p));
    return a;
}
__device__ __forceinline__ void ldm_x4(uint32_t* r, uint32_t addr) {
    asm volatile("ldmatrix.sync.aligned.m8n8.x4.shared.b16 {%0,%1,%2,%3}, [%4];"
        : "=r"(r[0]), "=r"(r[1]), "=r"(r[2]), "=r"(r[3]) : "r"(addr));
}
__device__ __forceinline__ void mma_bf16(float* c, const uint32_t* a, const uint32_t* b) {
    asm volatile("mma.sync.aligned.m16n8k16.row.col.f32.bf16.bf16.f32 "
        "{%0,%1,%2,%3}, {%4,%5,%6,%7}, {%8,%9}, {%0,%1,%2,%3};"
        : "+f"(c[0]), "+f"(c[1]), "+f"(c[2]), "+f"(c[3])
        : "r"(a[0]), "r"(a[1]), "r"(a[2]), "r"(a[3]), "r"(b[0]), "r"(b[1]));
}
__device__ __forceinline__ void split_bf16(float v, __nv_bfloat16& hi, __nv_bfloat16& lo) {
    hi = __float2bfloat16(v);
    lo = __float2bfloat16(v - __bfloat162float(hi));
}

// ---------------- small kernels ----------------

// Transpose fp32 weight [K,128] -> bf16 hi/lo [128,K] K-major (optional 0/1-block row permute)
__global__ void prep_w_kernel(const float* __restrict__ W, int K,
                              __nv_bfloat16* __restrict__ Th, __nv_bfloat16* __restrict__ Tl,
                              int perm)
{
    int k = blockIdx.x;
    int n = threadIdx.x;
    int ks = k;
    if (perm) { if (k < 128) ks = k + 128; else if (k < 256) ks = k - 128; }
    float v = W[ks * 128 + n];
    __nv_bfloat16 hi, lo; split_bf16(v, hi, lo);
    Th[(long)n * K + k] = hi;
    Tl[(long)n * K + k] = lo;
}

// Gather memory rows + time encoding + embedding splits -> bf16 hi/lo buffers
__global__ void gather_kernel(const int* __restrict__ src, const int* __restrict__ dst,
                              const float* __restrict__ mem, const float* __restrict__ edge,
                              const float* __restrict__ ts, const float* __restrict__ tw,
                              const float* __restrict__ tb,
                              const float* __restrict__ semb, const float* __restrict__ demb)
{
    int r = blockIdx.x;
    int j = threadIdx.x;
    int s = src[r], d = dst[r];
    long gb = (long)r * CONCATD;
    __nv_bfloat16 hi, lo;

    split_bf16(mem[(long)s * MEMD + j], hi, lo);
    g_Gh[gb + j] = hi; g_Gl[gb + j] = lo;
    split_bf16(mem[(long)d * MEMD + j], hi, lo);
    g_Gh[gb + 128 + j] = hi; g_Gl[gb + 128 + j] = lo;
    split_bf16(edge[(long)r * MEMD + j], hi, lo);
    g_Gh[gb + 256 + j] = hi; g_Gl[gb + 256 + j] = lo;
    if (j < TIMED) {
        float te = cosf(ts[r] * tw[j] + tb[j]);
        split_bf16(te, hi, lo);
        g_Gh[gb + 384 + j] = hi; g_Gl[gb + 384 + j] = lo;
        g_th[(long)r * TIMED + j] = hi; g_tl[(long)r * TIMED + j] = lo;
    }
    split_bf16(semb[(long)r * MEMD + j], hi, lo);
    g_seh[(long)r * MEMD + j] = hi; g_sel[(long)r * MEMD + j] = lo;
    split_bf16(demb[(long)r * MEMD + j], hi, lo);
    g_deh[(long)r * MEMD + j] = hi; g_del[(long)r * MEMD + j] = lo;
}

// ---------------- HMMA stage GEMM ----------------
struct BranchArgs {
    const __nv_bfloat16 *A0h, *A0l, *A1h, *A1l;   // A segments (widths w0 | w1)
    const __nv_bfloat16 *Wh, *Wl;                 // [128, K] K-major (== B col-major)
    const float* bias;
    __nv_bfloat16 *Ch, *Cl;                       // bf16 hi/lo out (may be null)
    float* Cf;                                    // fp32 out (may be null)
};

// load a 128-row x 64-col bf16 chunk (2 global segments, zero pad past K)
// into padded smem [128][SMS]
__device__ __forceinline__ void load_chunk(__nv_bfloat16* smdst,
                                           const __nv_bfloat16* __restrict__ A0,
                                           const __nv_bfloat16* __restrict__ A1,
                                           int w0, int w1, int K, int kb, int brow, int tid)
{
    #pragma unroll 4
    for (int idx = tid; idx < 128 * 32; idx += 256) {
        int r = idx >> 5;          // row 0..127
        int p = idx & 31;          // bf16x2 pair 0..31
        int gk = kb + (p << 1);
        uint32_t val = 0;
        if (gk < K) {
            if (gk < w0) val = *(const uint32_t*)(A0 + (size_t)(brow + r) * w0 + gk);
            else         val = *(const uint32_t*)(A1 + (size_t)(brow + r) * w1 + (gk - w0));
        }
        *(uint32_t*)(smdst + r * SMS + (p << 1)) = val;
    }
}

__global__ __launch_bounds__(256, 1)
void stage_gemm_kernel(BranchArgs bu, BranchArgs bi, int w0, int w1, int K, int relu)
{
    extern __shared__ __nv_bfloat16 sm[];
    __nv_bfloat16* Ah = sm;
    __nv_bfloat16* Al = sm + 128 * SMS;
    __nv_bfloat16* Wh = sm + 2 * 128 * SMS;
    __nv_bfloat16* Wl = sm + 3 * 128 * SMS;

    const BranchArgs P = blockIdx.y ? bi : bu;
    const int tid = threadIdx.x;
    const int lane = tid & 31;
    const int wid = tid >> 5;
    const int wm = (wid & 3) * 32;     // warp M offset (4 warps in M)
    const int wn = (wid >> 2) * 64;    // warp N offset (2 warps in N)
    const int brow = blockIdx.x * 128;

    float acc[2][8][4];
    #pragma unroll
    for (int i = 0; i < 2; i++)
        #pragma unroll
        for (int j = 0; j < 8; j++)
            #pragma unroll
            for (int k = 0; k < 4; k++) acc[i][j][k] = 0.f;

    // fragment load address components
    const int arow = (lane & 7) + ((lane >> 3) & 1) * 8;
    const int akoff = (lane >> 4) * 8;
    const int brow2 = ((lane >> 4) << 3) + (lane & 7);
    const int bkoff = ((lane >> 3) & 1) * 8;

    const int nCh = (K + 63) >> 6;
    for (int c = 0; c < nCh; c++) {
        int kb = c << 6;
        load_chunk(Ah, P.A0h, P.A1h, w0, w1, K, kb, brow, tid);
        load_chunk(Al, P.A0l, P.A1l, w0, w1, K, kb, brow, tid);
        load_chunk(Wh, P.Wh, (const __nv_bfloat16*)0, K, 0, K, kb, 0, tid);
        load_chunk(Wl, P.Wl, (const __nv_bfloat16*)0, K, 0, K, kb, 0, tid);
        __syncthreads();

        #pragma unroll
        for (int kk = 0; kk < 64; kk += 16) {
            uint32_t ah[2][4], al[2][4], bh[8][2], bl[8][2];
            #pragma unroll
            for (int mi = 0; mi < 2; mi++) {
                ldm_x4(ah[mi], smem_u32(Ah + (wm + mi * 16 + arow) * SMS + kk + akoff));
                ldm_x4(al[mi], smem_u32(Al + (wm + mi * 16 + arow) * SMS + kk + akoff));
            }
            #pragma unroll
            for (int nb = 0; nb < 4; nb++) {
                uint32_t r[4];
                ldm_x4(r, smem_u32(Wh + (wn + nb * 16 + brow2) * SMS + kk + bkoff));
                bh[nb * 2][0] = r[0]; bh[nb * 2][1] = r[1];
                bh[nb * 2 + 1][0] = r[2]; bh[nb * 2 + 1][1] = r[3];
                ldm_x4(r, smem_u32(Wl + (wn + nb * 16 + brow2) * SMS + kk + bkoff));
                bl[nb * 2][0] = r[0]; bl[nb * 2][1] = r[1];
                bl[nb * 2 + 1][0] = r[2]; bl[nb * 2 + 1][1] = r[3];
            }
            #pragma unroll
            for (int mi = 0; mi < 2; mi++)
                #pragma unroll
                for (int ni = 0; ni < 8; ni++) {
                    mma_bf16(acc[mi][ni], ah[mi], bh[ni]);
                    mma_bf16(acc[mi][ni], ah[mi], bl[ni]);
                    mma_bf16(acc[mi][ni], al[mi], bh[ni]);
                }
        }
        __syncthreads();
    }

    // epilogue: bias + relu, write straight from registers
    const int g = lane >> 2, q = lane & 3;
    #pragma unroll
    for (int mi = 0; mi < 2; mi++) {
        #pragma unroll
        for (int ni = 0; ni < 8; ni++) {
            int col = wn + ni * 8 + q * 2;
            float bv0 = P.bias[col], bv1 = P.bias[col + 1];
            #pragma unroll
            for (int h = 0; h < 2; h++) {
                long row = brow + wm + mi * 16 + g + h * 8;
                float v0 = acc[mi][ni][h * 2] + bv0;
                float v1 = acc[mi][ni][h * 2 + 1] + bv1;
                if (relu) { v0 = fmaxf(v0, 0.f); v1 = fmaxf(v1, 0.f); }
                if (P.Ch) {
                    __nv_bfloat16 h0, l0, h1, l1;
                    split_bf16(v0, h0, l0);
                    split_bf16(v1, h1, l1);
                    *(__nv_bfloat162*)(P.Ch + row * 128 + col) = __halves2bfloat162(h0, h1);
                    *(__nv_bfloat162*)(P.Cl + row * 128 + col) = __halves2bfloat162(l0, l1);
                }
                if (P.Cf)
                    *(float2*)(P.Cf + row * 128 + col) = make_float2(v0, v1);
            }
        }
    }
}

// ---------------- scatter (deterministic last-wins) ----------------
__global__ void win_init_kernel(int nodes)
{
    int i = blockIdx.x * blockDim.x + threadIdx.x;
    if (i < nodes) g_win[i] = -1;
}
__global__ void win_mark_kernel(const int* __restrict__ src, const int* __restrict__ dst, int Bn)
{
    int i = blockIdx.x * blockDim.x + threadIdx.x;
    if (i < 2 * Bn) {
        int id = (i < Bn) ? src[i] : dst[i - Bn];
        atomicMax(&g_win[id], i);
    }
}
__global__ void scatter_write_kernel(const int* __restrict__ src, const int* __restrict__ dst,
                                     float* __restrict__ out_mem, int Bn)
{
    int i = blockIdx.x;
    int j = threadIdx.x;
    int id;
    const float* row;
    if (i < Bn) { id = src[i];      row = g_ut + (long)i * MEMD; }
    else        { id = dst[i - Bn]; row = g_it + (long)(i - Bn) * MEMD; }
    if (g_win[id] == i)
        out_mem[(long)id * MEMD + j] = row[j];
}

// ---------------- launch ----------------
extern "C" void kernel_launch(void* const* d_in, const int* in_sizes, int n_in,
                              void* d_out, int out_size)
{
    const float* src_emb = (const float*)d_in[0];
    const float* dst_emb = (const float*)d_in[1];
    const int*   src_ids = (const int*)  d_in[2];
    const int*   dst_ids = (const int*)  d_in[3];
    const float* edge    = (const float*)d_in[4];
    const float* ts      = (const float*)d_in[5];
    const float* memory  = (const float*)d_in[6];
    const float* tw      = (const float*)d_in[7];
    const float* tb      = (const float*)d_in[8];
    const float* Wu1 = (const float*)d_in[9];   const float* bu1 = (const float*)d_in[10];
    const float* Wu2 = (const float*)d_in[11];  const float* bu2 = (const float*)d_in[12];
    const float* Wi1 = (const float*)d_in[13];  const float* bi1 = (const float*)d_in[14];
    const float* Wi2 = (const float*)d_in[15];  const float* bi2 = (const float*)d_in[16];
    const float* Wp1 = (const float*)d_in[17];  const float* bp1 = (const float*)d_in[18];
    const float* Wp2 = (const float*)d_in[19];  const float* bp2 = (const float*)d_in[20];
    const float* Wt1 = (const float*)d_in[21];  const float* bt1 = (const float*)d_in[22];
    const float* Wo  = (const float*)d_in[23];  const float* bo  = (const float*)d_in[24];

    const int Bn    = in_sizes[5];
    const int nodes = in_sizes[6] / MEMD;
    float* out = (float*)d_out;

    __nv_bfloat16 *Gh, *Gl, *th_, *tl_, *seh, *sel_, *deh, *del_;
    __nv_bfloat16 *auh, *aul, *aih, *ail, *buh, *bul, *bih, *bil;
    __nv_bfloat16 *uth, *utl, *ith, *itl, *wth, *wtl;
    float *ut, *it;
    cudaGetSymbolAddress((void**)&Gh, g_Gh);   cudaGetSymbolAddress((void**)&Gl, g_Gl);
    cudaGetSymbolAddress((void**)&th_, g_th);  cudaGetSymbolAddress((void**)&tl_, g_tl);
    cudaGetSymbolAddress((void**)&seh, g_seh); cudaGetSymbolAddress((void**)&sel_, g_sel);
    cudaGetSymbolAddress((void**)&deh, g_deh); cudaGetSymbolAddress((void**)&del_, g_del);
    cudaGetSymbolAddress((void**)&auh, g_auh); cudaGetSymbolAddress((void**)&aul, g_aul);
    cudaGetSymbolAddress((void**)&aih, g_aih); cudaGetSymbolAddress((void**)&ail, g_ail);
    cudaGetSymbolAddress((void**)&buh, g_buh); cudaGetSymbolAddress((void**)&bul, g_bul);
    cudaGetSymbolAddress((void**)&bih, g_bih); cudaGetSymbolAddress((void**)&bil, g_bil);
    cudaGetSymbolAddress((void**)&uth, g_uth); cudaGetSymbolAddress((void**)&utl, g_utl);
    cudaGetSymbolAddress((void**)&ith, g_ith); cudaGetSymbolAddress((void**)&itl, g_itl);
    cudaGetSymbolAddress((void**)&wth, g_wth); cudaGetSymbolAddress((void**)&wtl, g_wtl);
    cudaGetSymbolAddress((void**)&ut, g_ut);   cudaGetSymbolAddress((void**)&it, g_it);

    const int SMEM_DYN = 4 * 128 * SMS * (int)sizeof(__nv_bfloat16);  // 73728
    cudaFuncSetAttribute(stage_gemm_kernel, cudaFuncAttributeMaxDynamicSharedMemorySize, SMEM_DYN);

    // weight prep (transpose + bf16 split; Wi1 gets the 0/1 block swap)
    prep_w_kernel<<<484, 128>>>(Wu1, 484, wth + OFF_WU1, wtl + OFF_WU1, 0);
    prep_w_kernel<<<484, 128>>>(Wi1, 484, wth + OFF_WI1, wtl + OFF_WI1, 1);
    prep_w_kernel<<<128, 128>>>(Wu2, 128, wth + OFF_WU2, wtl + OFF_WU2, 0);
    prep_w_kernel<<<128, 128>>>(Wi2, 128, wth + OFF_WI2, wtl + OFF_WI2, 0);
    prep_w_kernel<<<128, 128>>>(Wp1, 128, wth + OFF_WP1, wtl + OFF_WP1, 0);
    prep_w_kernel<<<128, 128>>>(Wp2, 128, wth + OFF_WP2, wtl + OFF_WP2, 0);
    prep_w_kernel<<<228, 128>>>(Wt1, 228, wth + OFF_WT1, wtl + OFF_WT1, 0);
    prep_w_kernel<<<256, 128>>>(Wo,  256, wth + OFF_WO,  wtl + OFF_WO,  0);

    // gather + time encoding + splits
    gather_kernel<<<Bn, 128>>>(src_ids, dst_ids, memory, edge, ts, tw, tb, src_emb, dst_emb);

    const dim3 grid(Bn / 128, 2);
    BranchArgs U, I;

    // S1: K=484, relu -> a
    U = { Gh, Gl, 0, 0, wth + OFF_WU1, wtl + OFF_WU1, bu1, auh, aul, 0 };
    I = { Gh, Gl, 0, 0, wth + OFF_WI1, wtl + OFF_WI1, bi1, aih, ail, 0 };
    stage_gemm_kernel<<<grid, 256, SMEM_DYN>>>(U, I, CONCATD, 0, CONCATD, 1);
    // S2: K=128 -> b
    U = { auh, aul, 0, 0, wth + OFF_WU2, wtl + OFF_WU2, bu2, buh, bul, 0 };
    I = { aih, ail, 0, 0, wth + OFF_WI2, wtl + OFF_WI2, bi2, bih, bil, 0 };
    stage_gemm_kernel<<<grid, 256, SMEM_DYN>>>(U, I, 128, 0, 128, 0);
    // S3: shared proj layer1, relu -> a
    U = { buh, bul, 0, 0, wth + OFF_WP1, wtl + OFF_WP1, bp1, auh, aul, 0 };
    I = { bih, bil, 0, 0, wth + OFF_WP1, wtl + OFF_WP1, bp1, aih, ail, 0 };
    stage_gemm_kernel<<<grid, 256, SMEM_DYN>>>(U, I, 128, 0, 128, 1);
    // S4: shared proj layer2 -> b
    U = { auh, aul, 0, 0, wth + OFF_WP2, wtl + OFF_WP2, bp2, buh, bul, 0 };
    I = { aih, ail, 0, 0, wth + OFF_WP2, wtl + OFF_WP2, bp2, bih, bil, 0 };
    stage_gemm_kernel<<<grid, 256, SMEM_DYN>>>(U, I, 128, 0, 128, 0);
    // S5: t-batch [proj | time], K=228, relu -> ut/it (fp32 + hi/lo)
    U = { buh, bul, th_, tl_, wth + OFF_WT1, wtl + OFF_WT1, bt1, uth, utl, ut };
    I = { bih, bil, th_, tl_, wth + OFF_WT1, wtl + OFF_WT1, bt1, ith, itl, it };
    stage_gemm_kernel<<<grid, 256, SMEM_DYN>>>(U, I, 128, TIMED, 128 + TIMED, 1);
    // S6: output proj [t | emb], K=256 -> d_out
    U = { uth, utl, seh, sel_, wth + OFF_WO, wtl + OFF_WO, bo, 0, 0, out };
    I = { ith, itl, deh, del_, wth + OFF_WO, wtl + OFF_WO, bo, 0, 0, out + (long)Bn * MEMD };
    stage_gemm_kernel<<<grid, 256, SMEM_DYN>>>(U, I, 128, 128, 256, 0);

    // new_memory: copy bank + deterministic last-wins scatter
    long outHead = (long)2 * Bn * MEMD;
    if ((long)out_size >= outHead + (long)nodes * MEMD) {
        float* out_mem = out + outHead;
        cudaMemcpyAsync(out_mem, memory, (size_t)nodes * MEMD * sizeof(float),
                        cudaMemcpyDeviceToDevice);
        win_init_kernel<<<(nodes + 255) / 256, 256>>>(nodes);
        win_mark_kernel<<<(2 * Bn + 255) / 256, 256>>>(src_ids, dst_ids, Bn);
        scatter_write_kernel<<<2 * Bn, MEMD>>>(src_ids, dst_ids, out_mem, Bn);
    }
}

// round 5
// speedup vs baseline: 1.9857x; 1.7734x over previous
#include <cuda_runtime.h>
#include <cuda_bf16.h>
#include <math.h>
#include <stdint.h>

// ---------------- problem constants ----------------
#define BB       16384
#define MEMD     128
#define TIMED    100
#define MAXNODES 1100000

// ---------------- device scratch ----------------
__device__ float g_ut[BB * MEMD];
__device__ float g_it[BB * MEMD];
__device__ int   g_win[MAXNODES];

// ---------------- helpers ----------------
__device__ __forceinline__ uint32_t smem_u32(const void* p) {
    uint32_t a;
    asm("{ .reg .u64 t; cvta.to.shared.u64 t, %1; cvt.u32.u64 %0, t; }" : "=r"(a) : "l"(p));
    return a;
}
__device__ __forceinline__ void ldm_x4(uint32_t* r, uint32_t addr) {
    asm volatile("ldmatrix.sync.aligned.m8n8.x4.shared.b16 {%0,%1,%2,%3}, [%4];"
        : "=r"(r[0]), "=r"(r[1]), "=r"(r[2]), "=r"(r[3]) : "r"(addr));
}
__device__ __forceinline__ void mma_bf16(float* c, const uint32_t* a, const uint32_t* b) {
    asm volatile("mma.sync.aligned.m16n8k16.row.col.f32.bf16.bf16.f32 "
        "{%0,%1,%2,%3}, {%4,%5,%6,%7}, {%8,%9}, {%0,%1,%2,%3};"
        : "+f"(c[0]), "+f"(c[1]), "+f"(c[2]), "+f"(c[3])
        : "r"(a[0]), "r"(a[1]), "r"(a[2]), "r"(a[3]), "r"(b[0]), "r"(b[1]));
}
__device__ __forceinline__ void split2(float v0, float v1, uint32_t& hi, uint32_t& lo) {
    __nv_bfloat16 h0 = __float2bfloat16(v0);
    __nv_bfloat16 h1 = __float2bfloat16(v1);
    __nv_bfloat16 l0 = __float2bfloat16(v0 - __bfloat162float(h0));
    __nv_bfloat16 l1 = __float2bfloat16(v1 - __bfloat162float(h1));
    __nv_bfloat162 H = __halves2bfloat162(h0, h1);
    __nv_bfloat162 L = __halves2bfloat162(l0, l1);
    hi = *(uint32_t*)&H; lo = *(uint32_t*)&L;
}

// ---------------- fused chain kernel ----------------
// Per CTA: 128 rows, one branch (blockIdx.y: 0=user, 1=item).
// Stages: S0 [gather484]@W1 relu -> S1 @W2 -> S2 @Wp1 relu -> S3 @Wp2 ->
//         S4 [act|time]@Wt1 relu (writes fp32 ut/it) -> S5 [act|emb]@Wo (writes d_out)
struct ChainArgs {
    const int* ida;          // first id column (src for user, dst for item)
    const int* idb;          // second id column
    const float* emb;        // output-proj second segment
    const float* W[6];       // fp32 weights [K,128] row-major
    const float* bias[6];
    float* ut;               // stage-4 fp32 out
    float* outp;             // stage-5 fp32 out
};

// dyn smem layout (bf16 elements)
#define ACT_STR 136
#define CH_STR  72
#define OFF_ACT_H 0
#define OFF_ACT_L (128*ACT_STR)
#define OFF_CHA_H (2*128*ACT_STR)
#define OFF_CHA_L (OFF_CHA_H + 128*CH_STR)
#define OFF_CHW_H (OFF_CHA_L + 128*CH_STR)
#define OFF_CHW_L (OFF_CHW_H + 128*CH_STR)
#define SMEM_ELE  (OFF_CHW_L + 128*CH_STR)

__global__ __launch_bounds__(256, 1)
void chain_kernel(ChainArgs au, ChainArgs ai,
                  const float* __restrict__ memory,
                  const float* __restrict__ edge,
                  const float* __restrict__ ts,
                  const float* __restrict__ tw,
                  const float* __restrict__ tb)
{
    extern __shared__ __nv_bfloat16 sm[];
    __nv_bfloat16* ACT_H = sm + OFF_ACT_H;
    __nv_bfloat16* ACT_L = sm + OFF_ACT_L;
    __nv_bfloat16* CHA_H = sm + OFF_CHA_H;
    __nv_bfloat16* CHA_L = sm + OFF_CHA_L;
    __nv_bfloat16* CHW_H = sm + OFF_CHW_H;
    __nv_bfloat16* CHW_L = sm + OFF_CHW_L;

    __shared__ int   ida_s[128], idb_s[128];
    __shared__ float ts_s[128], tw_s[TIMED], tb_s[TIMED];

    const ChainArgs P = blockIdx.y ? ai : au;
    const int tid  = threadIdx.x;
    const int lane = tid & 31;
    const int wid  = tid >> 5;
    const int wm   = (wid & 3) * 32;
    const int wn   = (wid >> 2) * 64;
    const int brow = blockIdx.x * 128;

    if (tid < 128) {
        ida_s[tid] = P.ida[brow + tid];
        idb_s[tid] = P.idb[brow + tid];
        ts_s[tid]  = ts[brow + tid];
    }
    if (tid < TIMED) { tw_s[tid] = tw[tid]; tb_s[tid] = tb[tid]; }
    __syncthreads();

    // fragment addressing (verified in round 4)
    const int arow  = (lane & 7) + ((lane >> 3) & 1) * 8;
    const int akoff = (lane >> 4) * 8;
    const int brw2  = ((lane >> 4) << 3) + (lane & 7);
    const int bkoff = ((lane >> 3) & 1) * 8;
    const int g = lane >> 2, q = lane & 3;

    const int Ks[6] = {484, 128, 128, 128, 228, 256};
    const int rl[6] = {1, 0, 1, 0, 1, 0};

    for (int s = 0; s < 6; s++) {
        const int K = Ks[s];
        const float* W = P.W[s];
        float acc[2][8][4];
        #pragma unroll
        for (int i = 0; i < 2; i++)
            #pragma unroll
            for (int j = 0; j < 8; j++)
                #pragma unroll
                for (int k = 0; k < 4; k++) acc[i][j][k] = 0.f;

        const int nch = (K + 63) >> 6;
        for (int c = 0; c < nch; c++) {
            const int kb = c << 6;
            const bool fromAct = (s > 0) && (kb < 128);

            if (!fromAct) {
                // stage A chunk: 128 rows x 32 col-pairs
                for (int idx = tid; idx < 4096; idx += 256) {
                    int r = idx >> 5, clp = idx & 31;
                    int gk = kb + (clp << 1);
                    float v0 = 0.f, v1 = 0.f;
                    if (s == 0) {
                        if (gk < 128) {
                            float2 t = *(const float2*)(memory + (size_t)ida_s[r] * 128 + gk);
                            v0 = t.x; v1 = t.y;
                        } else if (gk < 256) {
                            float2 t = *(const float2*)(memory + (size_t)idb_s[r] * 128 + (gk - 128));
                            v0 = t.x; v1 = t.y;
                        } else if (gk < 384) {
                            float2 t = *(const float2*)(edge + (size_t)(brow + r) * 128 + (gk - 256));
                            v0 = t.x; v1 = t.y;
                        } else if (gk < 484) {
                            int t0 = gk - 384;
                            v0 = cosf(ts_s[r] * tw_s[t0] + tb_s[t0]);
                            if (t0 + 1 < TIMED) v1 = cosf(ts_s[r] * tw_s[t0 + 1] + tb_s[t0 + 1]);
                        }
                    } else if (s == 4) {
                        int t0 = gk - 128;
                        if (t0 < TIMED)     v0 = cosf(ts_s[r] * tw_s[t0] + tb_s[t0]);
                        if (t0 + 1 < TIMED) v1 = cosf(ts_s[r] * tw_s[t0 + 1] + tb_s[t0 + 1]);
                    } else { // s == 5
                        int e0 = gk - 128;
                        if (e0 < 128) {
                            float2 t = *(const float2*)(P.emb + (size_t)(brow + r) * 128 + e0);
                            v0 = t.x; v1 = t.y;
                        }
                    }
                    uint32_t hi, lo; split2(v0, v1, hi, lo);
                    *(uint32_t*)(CHA_H + r * CH_STR + (clp << 1)) = hi;
                    *(uint32_t*)(CHA_L + r * CH_STR + (clp << 1)) = lo;
                }
            }
            // stage W chunk: 128 n x 32 k-pairs, read fp32 [K,128] row-major
            for (int idx = tid; idx < 4096; idx += 256) {
                int n = idx & 127, klp = idx >> 7;
                int gk = kb + (klp << 1);
                float v0 = (gk < K)     ? W[(size_t)gk * 128 + n]       : 0.f;
                float v1 = (gk + 1 < K) ? W[(size_t)(gk + 1) * 128 + n] : 0.f;
                uint32_t hi, lo; split2(v0, v1, hi, lo);
                *(uint32_t*)(CHW_H + n * CH_STR + (klp << 1)) = hi;
                *(uint32_t*)(CHW_L + n * CH_STR + (klp << 1)) = lo;
            }
            __syncthreads();

            const __nv_bfloat16* AbH = fromAct ? ACT_H : CHA_H;
            const __nv_bfloat16* AbL = fromAct ? ACT_L : CHA_L;
            const int astr = fromAct ? ACT_STR : CH_STR;
            const int acol = fromAct ? kb : 0;

            #pragma unroll
            for (int kk = 0; kk < 64; kk += 16) {
                uint32_t ah[2][4], al[2][4], bh[8][2], bl[8][2];
                #pragma unroll
                for (int mi = 0; mi < 2; mi++) {
                    ldm_x4(ah[mi], smem_u32(AbH + (wm + mi * 16 + arow) * astr + acol + kk + akoff));
                    ldm_x4(al[mi], smem_u32(AbL + (wm + mi * 16 + arow) * astr + acol + kk + akoff));
                }
                #pragma unroll
                for (int nb = 0; nb < 4; nb++) {
                    uint32_t r4[4];
                    ldm_x4(r4, smem_u32(CHW_H + (wn + nb * 16 + brw2) * CH_STR + kk + bkoff));
                    bh[nb * 2][0] = r4[0]; bh[nb * 2][1] = r4[1];
                    bh[nb * 2 + 1][0] = r4[2]; bh[nb * 2 + 1][1] = r4[3];
                    ldm_x4(r4, smem_u32(CHW_L + (wn + nb * 16 + brw2) * CH_STR + kk + bkoff));
                    bl[nb * 2][0] = r4[0]; bl[nb * 2][1] = r4[1];
                    bl[nb * 2 + 1][0] = r4[2]; bl[nb * 2 + 1][1] = r4[3];
                }
                #pragma unroll
                for (int mi = 0; mi < 2; mi++)
                    #pragma unroll
                    for (int ni = 0; ni < 8; ni++) {
                        mma_bf16(acc[mi][ni], ah[mi], bh[ni]);
                        mma_bf16(acc[mi][ni], ah[mi], bl[ni]);
                        mma_bf16(acc[mi][ni], al[mi], bh[ni]);
                    }
            }
            __syncthreads();
        }

        // epilogue: bias (+relu); write ACT smem (stages 0-4), fp32 outs (4,5)
        const float* bias = P.bias[s];
        #pragma unroll
        for (int mi = 0; mi < 2; mi++) {
            #pragma unroll
            for (int ni = 0; ni < 8; ni++) {
                int col = wn + ni * 8 + q * 2;
                float bv0 = bias[col], bv1 = bias[col + 1];
                #pragma unroll
                for (int h = 0; h < 2; h++) {
                    int row = wm + mi * 16 + g + h * 8;
                    float v0 = acc[mi][ni][h * 2] + bv0;
                    float v1 = acc[mi][ni][h * 2 + 1] + bv1;
                    if (rl[s]) { v0 = fmaxf(v0, 0.f); v1 = fmaxf(v1, 0.f); }
                    if (s < 5) {
                        uint32_t hi, lo; split2(v0, v1, hi, lo);
                        *(uint32_t*)(ACT_H + row * ACT_STR + col) = hi;
                        *(uint32_t*)(ACT_L + row * ACT_STR + col) = lo;
                        if (s == 4)
                            *(float2*)(P.ut + (size_t)(brow + row) * 128 + col) = make_float2(v0, v1);
                    } else {
                        *(float2*)(P.outp + (size_t)(brow + row) * 128 + col) = make_float2(v0, v1);
                    }
                }
            }
        }
        __syncthreads();
    }
}

// ---------------- scatter winner + merged memory output ----------------
__global__ void win_init_kernel(int nodes)
{
    int i = blockIdx.x * blockDim.x + threadIdx.x;
    if (i < nodes) g_win[i] = -1;
}
__global__ void win_mark_kernel(const int* __restrict__ src, const int* __restrict__ dst, int Bn)
{
    int i = blockIdx.x * blockDim.x + threadIdx.x;
    if (i < 2 * Bn) {
        int id = (i < Bn) ? src[i] : dst[i - Bn];
        atomicMax(&g_win[id], i);
    }
}
// new_memory in one pass: winner rows take t-batch output, others copy memory.
__global__ void merge_out_kernel(const float4* __restrict__ mem4,
                                 float4* __restrict__ out4,
                                 const float* __restrict__ ut,
                                 const float* __restrict__ it,
                                 int Bn, int nodes)
{
    size_t idx = (size_t)blockIdx.x * blockDim.x + threadIdx.x;
    if (idx >= (size_t)nodes * 32) return;
    int row = (int)(idx >> 5);
    int sub = (int)(idx & 31);
    int w = g_win[row];
    float4 v;
    if (w < 0) {
        v = mem4[idx];
    } else {
        const float* srow = (w < Bn) ? ut + (size_t)w * 128 : it + (size_t)(w - Bn) * 128;
        v = *(const float4*)(srow + sub * 4);
    }
    out4[idx] = v;
}

// ---------------- launch ----------------
extern "C" void kernel_launch(void* const* d_in, const int* in_sizes, int n_in,
                              void* d_out, int out_size)
{
    const float* src_emb = (const float*)d_in[0];
    const float* dst_emb = (const float*)d_in[1];
    const int*   src_ids = (const int*)  d_in[2];
    const int*   dst_ids = (const int*)  d_in[3];
    const float* edge    = (const float*)d_in[4];
    const float* ts      = (const float*)d_in[5];
    const float* memory  = (const float*)d_in[6];
    const float* tw      = (const float*)d_in[7];
    const float* tb      = (const float*)d_in[8];
    const float* Wu1 = (const float*)d_in[9];   const float* bu1 = (const float*)d_in[10];
    const float* Wu2 = (const float*)d_in[11];  const float* bu2 = (const float*)d_in[12];
    const float* Wi1 = (const float*)d_in[13];  const float* bi1 = (const float*)d_in[14];
    const float* Wi2 = (const float*)d_in[15];  const float* bi2 = (const float*)d_in[16];
    const float* Wp1 = (const float*)d_in[17];  const float* bp1 = (const float*)d_in[18];
    const float* Wp2 = (const float*)d_in[19];  const float* bp2 = (const float*)d_in[20];
    const float* Wt1 = (const float*)d_in[21];  const float* bt1 = (const float*)d_in[22];
    const float* Wo  = (const float*)d_in[23];  const float* bo  = (const float*)d_in[24];

    const int Bn    = in_sizes[5];
    const int nodes = in_sizes[6] / MEMD;
    float* out = (float*)d_out;

    float *ut, *it;
    cudaGetSymbolAddress((void**)&ut, g_ut);
    cudaGetSymbolAddress((void**)&it, g_it);

    const int SMEM_DYN = SMEM_ELE * (int)sizeof(__nv_bfloat16);
    cudaFuncSetAttribute(chain_kernel, cudaFuncAttributeMaxDynamicSharedMemorySize, SMEM_DYN);

    // winner computation (independent of chain; issue first)
    win_init_kernel<<<(nodes + 255) / 256, 256>>>(nodes);
    win_mark_kernel<<<(2 * Bn + 255) / 256, 256>>>(src_ids, dst_ids, Bn);

    // fused full chain: gather -> 6 GEMM stages -> ut/it + d_out head
    ChainArgs U, I;
    U.ida = src_ids; U.idb = dst_ids; U.emb = src_emb;
    U.W[0] = Wu1; U.W[1] = Wu2; U.W[2] = Wp1; U.W[3] = Wp2; U.W[4] = Wt1; U.W[5] = Wo;
    U.bias[0] = bu1; U.bias[1] = bu2; U.bias[2] = bp1; U.bias[3] = bp2; U.bias[4] = bt1; U.bias[5] = bo;
    U.ut = ut; U.outp = out;
    I.ida = dst_ids; I.idb = src_ids; I.emb = dst_emb;
    I.W[0] = Wi1; I.W[1] = Wi2; I.W[2] = Wp1; I.W[3] = Wp2; I.W[4] = Wt1; I.W[5] = Wo;
    I.bias[0] = bi1; I.bias[1] = bi2; I.bias[2] = bp1; I.bias[3] = bp2; I.bias[4] = bt1; I.bias[5] = bo;
    I.ut = it; I.outp = out + (size_t)Bn * MEMD;

    dim3 grid(Bn / 128, 2);
    chain_kernel<<<grid, 256, SMEM_DYN>>>(U, I, memory, edge, ts, tw, tb);

    // new_memory (copy + scatter fused, single pass)
    long outHead = (long)2 * Bn * MEMD;
    if ((long)out_size >= outHead + (long)nodes * MEMD) {
        float* out_mem = out + outHead;
        size_t total = (size_t)nodes * 32;
        merge_out_kernel<<<(unsigned)((total + 255) / 256), 256>>>(
            (const float4*)memory, (float4*)out_mem, ut, it, Bn, nodes);
    }
}

// round 6
// speedup vs baseline: 2.1515x; 1.0835x over previous
#include <cuda_runtime.h>
#include <cuda_bf16.h>
#include <math.h>
#include <stdint.h>

// ---------------- problem constants ----------------
#define BB       16384
#define MEMD     128
#define TIMED    100
#define MAXNODES 1100000

// ---------------- device scratch ----------------
__device__ float g_ut[BB * MEMD];
__device__ float g_it[BB * MEMD];
__device__ int   g_win[MAXNODES];
// pre-split bf16 weight pools, [128, Kp] K-major per weight, concatenated
#define POOL_ELE (2048 * 128)
__device__ __align__(16) __nv_bfloat16 g_wph[POOL_ELE];
__device__ __align__(16) __nv_bfloat16 g_wpl[POOL_ELE];
// pool bases (elements)
#define PB_U1 0
#define PB_I1 65536
#define PB_U2 131072
#define PB_I2 147456
#define PB_P1 163840
#define PB_P2 180224
#define PB_T1 196608
#define PB_O  229376

// ---------------- helpers ----------------
__device__ __forceinline__ uint32_t smem_u32(const void* p) {
    uint32_t a;
    asm("{ .reg .u64 t; cvta.to.shared.u64 t, %1; cvt.u32.u64 %0, t; }" : "=r"(a) : "l"(p));
    return a;
}
__device__ __forceinline__ void ldm_x4(uint32_t* r, uint32_t addr) {
    asm volatile("ldmatrix.sync.aligned.m8n8.x4.shared.b16 {%0,%1,%2,%3}, [%4];"
        : "=r"(r[0]), "=r"(r[1]), "=r"(r[2]), "=r"(r[3]) : "r"(addr));
}
__device__ __forceinline__ void mma_bf16(float* c, const uint32_t* a, const uint32_t* b) {
    asm volatile("mma.sync.aligned.m16n8k16.row.col.f32.bf16.bf16.f32 "
        "{%0,%1,%2,%3}, {%4,%5,%6,%7}, {%8,%9}, {%0,%1,%2,%3};"
        : "+f"(c[0]), "+f"(c[1]), "+f"(c[2]), "+f"(c[3])
        : "r"(a[0]), "r"(a[1]), "r"(a[2]), "r"(a[3]), "r"(b[0]), "r"(b[1]));
}
__device__ __forceinline__ void cp16(uint32_t smaddr, const void* g) {
    asm volatile("cp.async.ca.shared.global [%0], [%1], 16;" :: "r"(smaddr), "l"(g));
}
__device__ __forceinline__ void split2(float v0, float v1, uint32_t& hi, uint32_t& lo) {
    __nv_bfloat16 h0 = __float2bfloat16(v0);
    __nv_bfloat16 h1 = __float2bfloat16(v1);
    __nv_bfloat16 l0 = __float2bfloat16(v0 - __bfloat162float(h0));
    __nv_bfloat16 l1 = __float2bfloat16(v1 - __bfloat162float(h1));
    __nv_bfloat162 H = __halves2bfloat162(h0, h1);
    __nv_bfloat162 L = __halves2bfloat162(l0, l1);
    hi = *(uint32_t*)&H; lo = *(uint32_t*)&L;
}

// ---------------- weight prep: fp32 [K,128] -> bf16 hi/lo [128,Kp] K-major ----
__global__ void prep_w_kernel(const float* __restrict__ W, int K, int Kp, int base)
{
    int k = blockIdx.x;      // 0..Kp-1
    int n = threadIdx.x;     // 0..127
    float v = (k < K) ? W[(size_t)k * 128 + n] : 0.f;
    __nv_bfloat16 hi = __float2bfloat16(v);
    __nv_bfloat16 lo = __float2bfloat16(v - __bfloat162float(hi));
    g_wph[base + (size_t)n * Kp + k] = hi;
    g_wpl[base + (size_t)n * Kp + k] = lo;
}

// ---------------- fused chain kernel ----------------
struct ChainArgs {
    const int* ida;
    const int* idb;
    const float* emb;
    int wbase[6];            // pool base per stage
    int kp[6];               // padded K per stage
    const float* bias[6];
    float* ut;
    float* outp;
};

#define ACT_STR 136
#define CH_STR  72
#define OFF_ACT_H 0
#define OFF_ACT_L (128*ACT_STR)
#define OFF_CHA_H (2*128*ACT_STR)
#define OFF_CHA_L (OFF_CHA_H + 128*CH_STR)
#define OFF_CHW_H (OFF_CHA_L + 128*CH_STR)
#define OFF_CHW_L (OFF_CHW_H + 128*CH_STR)
#define SMEM_ELE  (OFF_CHW_L + 128*CH_STR)

__global__ __launch_bounds__(256, 1)
void chain_kernel(ChainArgs au, ChainArgs ai,
                  const float* __restrict__ memory,
                  const float* __restrict__ edge,
                  const float* __restrict__ ts,
                  const float* __restrict__ tw,
                  const float* __restrict__ tb)
{
    extern __shared__ __nv_bfloat16 sm[];
    __nv_bfloat16* ACT_H = sm + OFF_ACT_H;
    __nv_bfloat16* ACT_L = sm + OFF_ACT_L;
    __nv_bfloat16* CHA_H = sm + OFF_CHA_H;
    __nv_bfloat16* CHA_L = sm + OFF_CHA_L;
    __nv_bfloat16* CHW_H = sm + OFF_CHW_H;
    __nv_bfloat16* CHW_L = sm + OFF_CHW_L;

    __shared__ int   ida_s[128], idb_s[128];
    __shared__ float ts_s[128], tw_s[TIMED], tb_s[TIMED];

    const ChainArgs P = blockIdx.y ? ai : au;
    const int tid  = threadIdx.x;
    const int lane = tid & 31;
    const int wid  = tid >> 5;
    const int wm   = (wid & 3) * 32;
    const int wn   = (wid >> 2) * 64;
    const int brow = blockIdx.x * 128;

    if (tid < 128) {
        ida_s[tid] = P.ida[brow + tid];
        idb_s[tid] = P.idb[brow + tid];
        ts_s[tid]  = ts[brow + tid];
    }
    if (tid < TIMED) { tw_s[tid] = tw[tid]; tb_s[tid] = tb[tid]; }
    __syncthreads();

    const int arow  = (lane & 7) + ((lane >> 3) & 1) * 8;
    const int akoff = (lane >> 4) * 8;
    const int brw2  = ((lane >> 4) << 3) + (lane & 7);
    const int bkoff = ((lane >> 3) & 1) * 8;
    const int g = lane >> 2, q = lane & 3;

    const int rl[6] = {1, 0, 1, 0, 1, 0};

    for (int s = 0; s < 6; s++) {
        const int Kp = P.kp[s];
        const __nv_bfloat16* WH = g_wph + P.wbase[s];
        const __nv_bfloat16* WL = g_wpl + P.wbase[s];
        float acc[2][8][4];
        #pragma unroll
        for (int i = 0; i < 2; i++)
            #pragma unroll
            for (int j = 0; j < 8; j++)
                #pragma unroll
                for (int k = 0; k < 4; k++) acc[i][j][k] = 0.f;

        const int nch = Kp >> 6;
        for (int c = 0; c < nch; c++) {
            const int kb = c << 6;
            const bool fromAct = (s > 0) && (kb < 128);

            // W chunk via cp.async (issue first; overlaps with A staging below)
            for (int idx = tid; idx < 1024; idx += 256) {
                int n = idx >> 3, seg = idx & 7;
                size_t go = (size_t)n * Kp + kb + seg * 8;
                uint32_t so = n * CH_STR + seg * 8;
                cp16(smem_u32(CHW_H + so), WH + go);
                cp16(smem_u32(CHW_L + so), WL + go);
            }
            asm volatile("cp.async.commit_group;" ::: "memory");

            if (!fromAct) {
                for (int idx = tid; idx < 4096; idx += 256) {
                    int r = idx >> 5, clp = idx & 31;
                    int gk = kb + (clp << 1);
                    float v0 = 0.f, v1 = 0.f;
                    if (s == 0) {
                        if (gk < 128) {
                            float2 t = *(const float2*)(memory + (size_t)ida_s[r] * 128 + gk);
                            v0 = t.x; v1 = t.y;
                        } else if (gk < 256) {
                            float2 t = *(const float2*)(memory + (size_t)idb_s[r] * 128 + (gk - 128));
                            v0 = t.x; v1 = t.y;
                        } else if (gk < 384) {
                            float2 t = *(const float2*)(edge + (size_t)(brow + r) * 128 + (gk - 256));
                            v0 = t.x; v1 = t.y;
                        } else if (gk < 484) {
                            int t0 = gk - 384;
                            v0 = cosf(ts_s[r] * tw_s[t0] + tb_s[t0]);
                            if (t0 + 1 < TIMED) v1 = cosf(ts_s[r] * tw_s[t0 + 1] + tb_s[t0 + 1]);
                        }
                    } else if (s == 4) {
                        int t0 = gk - 128;
                        if (t0 < TIMED)     v0 = cosf(ts_s[r] * tw_s[t0] + tb_s[t0]);
                        if (t0 + 1 < TIMED) v1 = cosf(ts_s[r] * tw_s[t0 + 1] + tb_s[t0 + 1]);
                    } else { // s == 5
                        int e0 = gk - 128;
                        if (e0 < 128) {
                            float2 t = *(const float2*)(P.emb + (size_t)(brow + r) * 128 + e0);
                            v0 = t.x; v1 = t.y;
                        }
                    }
                    uint32_t hi, lo; split2(v0, v1, hi, lo);
                    *(uint32_t*)(CHA_H + r * CH_STR + (clp << 1)) = hi;
                    *(uint32_t*)(CHA_L + r * CH_STR + (clp << 1)) = lo;
                }
            }
            asm volatile("cp.async.wait_group 0;" ::: "memory");
            __syncthreads();

            const __nv_bfloat16* AbH = fromAct ? ACT_H : CHA_H;
            const __nv_bfloat16* AbL = fromAct ? ACT_L : CHA_L;
            const int astr = fromAct ? ACT_STR : CH_STR;
            const int acol = fromAct ? kb : 0;

            #pragma unroll
            for (int kk = 0; kk < 64; kk += 16) {
                uint32_t ah[2][4], al[2][4], bh[8][2], bl[8][2];
                #pragma unroll
                for (int mi = 0; mi < 2; mi++) {
                    ldm_x4(ah[mi], smem_u32(AbH + (wm + mi * 16 + arow) * astr + acol + kk + akoff));
                    ldm_x4(al[mi], smem_u32(AbL + (wm + mi * 16 + arow) * astr + acol + kk + akoff));
                }
                #pragma unroll
                for (int nb = 0; nb < 4; nb++) {
                    uint32_t r4[4];
                    ldm_x4(r4, smem_u32(CHW_H + (wn + nb * 16 + brw2) * CH_STR + kk + bkoff));
                    bh[nb * 2][0] = r4[0]; bh[nb * 2][1] = r4[1];
                    bh[nb * 2 + 1][0] = r4[2]; bh[nb * 2 + 1][1] = r4[3];
                    ldm_x4(r4, smem_u32(CHW_L + (wn + nb * 16 + brw2) * CH_STR + kk + bkoff));
                    bl[nb * 2][0] = r4[0]; bl[nb * 2][1] = r4[1];
                    bl[nb * 2 + 1][0] = r4[2]; bl[nb * 2 + 1][1] = r4[3];
                }
                #pragma unroll
                for (int mi = 0; mi < 2; mi++)
                    #pragma unroll
                    for (int ni = 0; ni < 8; ni++) {
                        mma_bf16(acc[mi][ni], ah[mi], bh[ni]);
                        mma_bf16(acc[mi][ni], ah[mi], bl[ni]);
                        mma_bf16(acc[mi][ni], al[mi], bh[ni]);
                    }
            }
            __syncthreads();
        }

        const float* bias = P.bias[s];
        #pragma unroll
        for (int mi = 0; mi < 2; mi++) {
            #pragma unroll
            for (int ni = 0; ni < 8; ni++) {
                int col = wn + ni * 8 + q * 2;
                float bv0 = bias[col], bv1 = bias[col + 1];
                #pragma unroll
                for (int h = 0; h < 2; h++) {
                    int row = wm + mi * 16 + g + h * 8;
                    float v0 = acc[mi][ni][h * 2] + bv0;
                    float v1 = acc[mi][ni][h * 2 + 1] + bv1;
                    if (rl[s]) { v0 = fmaxf(v0, 0.f); v1 = fmaxf(v1, 0.f); }
                    if (s < 5) {
                        uint32_t hi, lo; split2(v0, v1, hi, lo);
                        *(uint32_t*)(ACT_H + row * ACT_STR + col) = hi;
                        *(uint32_t*)(ACT_L + row * ACT_STR + col) = lo;
                        if (s == 4)
                            *(float2*)(P.ut + (size_t)(brow + row) * 128 + col) = make_float2(v0, v1);
                    } else {
                        *(float2*)(P.outp + (size_t)(brow + row) * 128 + col) = make_float2(v0, v1);
                    }
                }
            }
        }
        __syncthreads();
    }
}

// ---------------- winner + memory output ----------------
__global__ void win_init_kernel(int nodes)
{
    int i = blockIdx.x * blockDim.x + threadIdx.x;
    if (i < nodes) g_win[i] = -1;
}
__global__ void win_mark_kernel(const int* __restrict__ src, const int* __restrict__ dst, int Bn)
{
    int i = blockIdx.x * blockDim.x + threadIdx.x;
    if (i < 2 * Bn) {
        int id = (i < Bn) ? src[i] : dst[i - Bn];
        atomicMax(&g_win[id], i);
    }
}
// copy all non-winner rows (runs concurrently with the chain)
__global__ void copy_pass_kernel(const float4* __restrict__ mem4,
                                 float4* __restrict__ out4, int nodes)
{
    size_t idx = (size_t)blockIdx.x * blockDim.x + threadIdx.x;
    if (idx >= (size_t)nodes * 32) return;
    int row = (int)(idx >> 5);
    if (g_win[row] >= 0) return;       // winner rows written later by scatter
    out4[idx] = mem4[idx];
}
// winner rows only (after chain): 2B candidate rows, ~disjoint from copy_pass writes
__global__ void scatter_win_kernel(const int* __restrict__ src, const int* __restrict__ dst,
                                   const float* __restrict__ ut, const float* __restrict__ it,
                                   float* __restrict__ out_mem, int Bn)
{
    int i = blockIdx.x;
    int j = threadIdx.x;
    int id;
    const float* row;
    if (i < Bn) { id = src[i];      row = ut + (size_t)i * 128; }
    else        { id = dst[i - Bn]; row = it + (size_t)(i - Bn) * 128; }
    if (g_win[id] == i)
        out_mem[(size_t)id * 128 + j] = row[j];
}

// ---------------- launch ----------------
extern "C" void kernel_launch(void* const* d_in, const int* in_sizes, int n_in,
                              void* d_out, int out_size)
{
    const float* src_emb = (const float*)d_in[0];
    const float* dst_emb = (const float*)d_in[1];
    const int*   src_ids = (const int*)  d_in[2];
    const int*   dst_ids = (const int*)  d_in[3];
    const float* edge    = (const float*)d_in[4];
    const float* ts      = (const float*)d_in[5];
    const float* memory  = (const float*)d_in[6];
    const float* tw      = (const float*)d_in[7];
    const float* tb      = (const float*)d_in[8];
    const float* Wu1 = (const float*)d_in[9];   const float* bu1 = (const float*)d_in[10];
    const float* Wu2 = (const float*)d_in[11];  const float* bu2 = (const float*)d_in[12];
    const float* Wi1 = (const float*)d_in[13];  const float* bi1 = (const float*)d_in[14];
    const float* Wi2 = (const float*)d_in[15];  const float* bi2 = (const float*)d_in[16];
    const float* Wp1 = (const float*)d_in[17];  const float* bp1 = (const float*)d_in[18];
    const float* Wp2 = (const float*)d_in[19];  const float* bp2 = (const float*)d_in[20];
    const float* Wt1 = (const float*)d_in[21];  const float* bt1 = (const float*)d_in[22];
    const float* Wo  = (const float*)d_in[23];  const float* bo  = (const float*)d_in[24];

    const int Bn    = in_sizes[5];
    const int nodes = in_sizes[6] / MEMD;
    float* out = (float*)d_out;

    float *ut, *it;
    cudaGetSymbolAddress((void**)&ut, g_ut);
    cudaGetSymbolAddress((void**)&it, g_it);

    const int SMEM_DYN = SMEM_ELE * (int)sizeof(__nv_bfloat16);
    cudaFuncSetAttribute(chain_kernel, cudaFuncAttributeMaxDynamicSharedMemorySize, SMEM_DYN);

    // one-time stream/event infra (created on the pre-capture correctness call)
    static cudaStream_t s2 = nullptr;
    static cudaEvent_t evFork = nullptr, evMark = nullptr, evCopy = nullptr;
    if (!s2) {
        cudaStreamCreateWithFlags(&s2, cudaStreamNonBlocking);
        cudaEventCreateWithFlags(&evFork, cudaEventDisableTiming);
        cudaEventCreateWithFlags(&evMark, cudaEventDisableTiming);
        cudaEventCreateWithFlags(&evCopy, cudaEventDisableTiming);
    }

    long outHead = (long)2 * Bn * MEMD;
    bool hasMem = ((long)out_size >= outHead + (long)nodes * MEMD);
    float* out_mem = out + outHead;

    // ---- fork side stream: winner calc + bulk copy, concurrent with chain ----
    cudaEventRecord(evFork, 0);
    cudaStreamWaitEvent(s2, evFork, 0);
    win_init_kernel<<<(nodes + 255) / 256, 256, 0, s2>>>(nodes);
    win_mark_kernel<<<(2 * Bn + 255) / 256, 256, 0, s2>>>(src_ids, dst_ids, Bn);
    cudaEventRecord(evMark, s2);
    if (hasMem) {
        size_t total = (size_t)nodes * 32;
        copy_pass_kernel<<<(unsigned)((total + 255) / 256), 256, 0, s2>>>(
            (const float4*)memory, (float4*)out_mem, nodes);
    }
    cudaEventRecord(evCopy, s2);

    // ---- main stream: weight prep + fused chain ----
    prep_w_kernel<<<512, 128>>>(Wu1, 484, 512, PB_U1);
    prep_w_kernel<<<512, 128>>>(Wi1, 484, 512, PB_I1);
    prep_w_kernel<<<128, 128>>>(Wu2, 128, 128, PB_U2);
    prep_w_kernel<<<128, 128>>>(Wi2, 128, 128, PB_I2);
    prep_w_kernel<<<128, 128>>>(Wp1, 128, 128, PB_P1);
    prep_w_kernel<<<128, 128>>>(Wp2, 128, 128, PB_P2);
    prep_w_kernel<<<256, 128>>>(Wt1, 228, 256, PB_T1);
    prep_w_kernel<<<256, 128>>>(Wo,  256, 256, PB_O);

    ChainArgs U, I;
    U.ida = src_ids; U.idb = dst_ids; U.emb = src_emb;
    int ubase[6] = {PB_U1, PB_U2, PB_P1, PB_P2, PB_T1, PB_O};
    int ibase[6] = {PB_I1, PB_I2, PB_P1, PB_P2, PB_T1, PB_O};
    int kps[6]   = {512, 128, 128, 128, 256, 256};
    for (int s = 0; s < 6; s++) { U.wbase[s] = ubase[s]; I.wbase[s] = ibase[s]; U.kp[s] = I.kp[s] = kps[s]; }
    U.bias[0] = bu1; U.bias[1] = bu2; U.bias[2] = bp1; U.bias[3] = bp2; U.bias[4] = bt1; U.bias[5] = bo;
    I.bias[0] = bi1; I.bias[1] = bi2; I.bias[2] = bp1; I.bias[3] = bp2; I.bias[4] = bt1; I.bias[5] = bo;
    U.ut = ut; U.outp = out;
    I.ida = dst_ids; I.idb = src_ids; I.emb = dst_emb;
    I.ut = it; I.outp = out + (size_t)Bn * MEMD;

    dim3 grid(Bn / 128, 2);
    chain_kernel<<<grid, 256, SMEM_DYN>>>(U, I, memory, edge, ts, tw, tb);

    // ---- join: winner scatter needs chain output + g_win ----
    if (hasMem) {
        cudaStreamWaitEvent(0, evMark, 0);
        scatter_win_kernel<<<2 * Bn, 128>>>(src_ids, dst_ids, ut, it, out_mem, Bn);
    }
    cudaStreamWaitEvent(0, evCopy, 0);
}

// round 7
// speedup vs baseline: 2.9301x; 1.3619x over previous
#include <cuda_runtime.h>
#include <cuda_bf16.h>
#include <math.h>
#include <stdint.h>

// ---------------- problem constants ----------------
#define BB       16384
#define MEMD     128
#define TIMED    100
#define MAXNODES 1100000

// ---------------- device scratch ----------------
__device__ float g_ut[BB * MEMD];
__device__ float g_it[BB * MEMD];
__device__ int   g_win[MAXNODES];
// pre-split bf16 weight pools, [128, Kp] K-major per weight, concatenated
#define POOL_ELE (2048 * 128)
__device__ __align__(16) __nv_bfloat16 g_wph[POOL_ELE];
__device__ __align__(16) __nv_bfloat16 g_wpl[POOL_ELE];
// pool bases (elements) ; padded K per weight: U1/I1=512, U2/I2/P1/P2=128, T1/O=256
#define PB_U1 0
#define PB_I1 65536
#define PB_U2 131072
#define PB_I2 147456
#define PB_P1 163840
#define PB_P2 180224
#define PB_T1 196608
#define PB_O  229376

// ---------------- helpers ----------------
__device__ __forceinline__ uint32_t smem_u32(const void* p) {
    uint32_t a;
    asm("{ .reg .u64 t; cvta.to.shared.u64 t, %1; cvt.u32.u64 %0, t; }" : "=r"(a) : "l"(p));
    return a;
}
__device__ __forceinline__ void ldm_x4(uint32_t* r, uint32_t addr) {
    asm volatile("ldmatrix.sync.aligned.m8n8.x4.shared.b16 {%0,%1,%2,%3}, [%4];"
        : "=r"(r[0]), "=r"(r[1]), "=r"(r[2]), "=r"(r[3]) : "r"(addr));
}
__device__ __forceinline__ void mma_bf16(float* c, const uint32_t* a, const uint32_t* b) {
    asm volatile("mma.sync.aligned.m16n8k16.row.col.f32.bf16.bf16.f32 "
        "{%0,%1,%2,%3}, {%4,%5,%6,%7}, {%8,%9}, {%0,%1,%2,%3};"
        : "+f"(c[0]), "+f"(c[1]), "+f"(c[2]), "+f"(c[3])
        : "r"(a[0]), "r"(a[1]), "r"(a[2]), "r"(a[3]), "r"(b[0]), "r"(b[1]));
}
__device__ __forceinline__ void cp16(uint32_t smaddr, const void* g) {
    asm volatile("cp.async.ca.shared.global [%0], [%1], 16;" :: "r"(smaddr), "l"(g));
}
__device__ __forceinline__ void split2(float v0, float v1, uint32_t& hi, uint32_t& lo) {
    __nv_bfloat16 h0 = __float2bfloat16(v0);
    __nv_bfloat16 h1 = __float2bfloat16(v1);
    __nv_bfloat16 l0 = __float2bfloat16(v0 - __bfloat162float(h0));
    __nv_bfloat16 l1 = __float2bfloat16(v1 - __bfloat162float(h1));
    __nv_bfloat162 H = __halves2bfloat162(h0, h1);
    __nv_bfloat162 L = __halves2bfloat162(l0, l1);
    hi = *(uint32_t*)&H; lo = *(uint32_t*)&L;
}

// ---------------- fused weight prep: all 8 weights in ONE launch ----------------
struct PrepArgs {
    const float* W[8];
    int K[8];     // true K
    int Kp[8];    // padded K
    int base[8];  // pool base
    int cum[9];   // cumulative Kp rows
};
__global__ void prep_all_kernel(PrepArgs pa)
{
    int kglob = blockIdx.x;  // 0..2047
    int n = threadIdx.x;     // 0..127
    int w = 0;
    #pragma unroll
    for (int i = 0; i < 8; i++) if (kglob >= pa.cum[i + 1]) w = i + 1;
    int k = kglob - pa.cum[w];
    float v = (k < pa.K[w]) ? pa.W[w][(size_t)k * 128 + n] : 0.f;
    __nv_bfloat16 hi = __float2bfloat16(v);
    __nv_bfloat16 lo = __float2bfloat16(v - __bfloat162float(hi));
    int Kp = pa.Kp[w];
    g_wph[pa.base[w] + (size_t)n * Kp + k] = hi;
    g_wpl[pa.base[w] + (size_t)n * Kp + k] = lo;
}

// ---------------- fused chain kernel (64-row CTAs, 2 CTA/SM) ----------------
struct ChainArgs {
    const int* ida;
    const int* idb;
    const float* emb;
    int wbase[6];
    int kp[6];
    const float* bias[6];
    float* ut;
    float* outp;
};

#define MROWS 64
#define ACT_STR 136
#define CH_STR  72
#define OFF_ACT_H 0
#define OFF_ACT_L (MROWS*ACT_STR)
#define OFF_CHA_H (2*MROWS*ACT_STR)
#define OFF_CHA_L (OFF_CHA_H + MROWS*CH_STR)
#define OFF_CHW_H (OFF_CHA_L + MROWS*CH_STR)
#define OFF_CHW_L (OFF_CHW_H + 128*CH_STR)
#define SMEM_ELE  (OFF_CHW_L + 128*CH_STR)

__global__ __launch_bounds__(256, 2)
void chain_kernel(ChainArgs au, ChainArgs ai,
                  const float* __restrict__ memory,
                  const float* __restrict__ edge,
                  const float* __restrict__ ts,
                  const float* __restrict__ tw,
                  const float* __restrict__ tb)
{
    extern __shared__ __nv_bfloat16 sm[];
    __nv_bfloat16* ACT_H = sm + OFF_ACT_H;
    __nv_bfloat16* ACT_L = sm + OFF_ACT_L;
    __nv_bfloat16* CHA_H = sm + OFF_CHA_H;
    __nv_bfloat16* CHA_L = sm + OFF_CHA_L;
    __nv_bfloat16* CHW_H = sm + OFF_CHW_H;
    __nv_bfloat16* CHW_L = sm + OFF_CHW_L;

    __shared__ int   ida_s[MROWS], idb_s[MROWS];
    __shared__ float ts_s[MROWS], tw_s[TIMED], tb_s[TIMED];

    const ChainArgs P = blockIdx.y ? ai : au;
    const int tid  = threadIdx.x;
    const int lane = tid & 31;
    const int wid  = tid >> 5;
    const int wm   = (wid & 3) * 16;   // 4 warps in M, 16 rows each
    const int wn   = (wid >> 2) * 64;  // 2 warps in N
    const int brow = blockIdx.x * MROWS;

    if (tid < MROWS) {
        ida_s[tid] = P.ida[brow + tid];
        idb_s[tid] = P.idb[brow + tid];
        ts_s[tid]  = ts[brow + tid];
    }
    if (tid >= 128 && tid < 128 + TIMED) {
        tw_s[tid - 128] = tw[tid - 128];
        tb_s[tid - 128] = tb[tid - 128];
    }
    __syncthreads();

    const int arow  = (lane & 7) + ((lane >> 3) & 1) * 8;
    const int akoff = (lane >> 4) * 8;
    const int brw2  = ((lane >> 4) << 3) + (lane & 7);
    const int bkoff = ((lane >> 3) & 1) * 8;
    const int g = lane >> 2, q = lane & 3;

    const int rl[6] = {1, 0, 1, 0, 1, 0};

    for (int s = 0; s < 6; s++) {
        const int Kp = P.kp[s];
        const __nv_bfloat16* WH = g_wph + P.wbase[s];
        const __nv_bfloat16* WL = g_wpl + P.wbase[s];
        float acc[8][4];
        #pragma unroll
        for (int j = 0; j < 8; j++)
            #pragma unroll
            for (int k = 0; k < 4; k++) acc[j][k] = 0.f;

        const int nch = Kp >> 6;
        for (int c = 0; c < nch; c++) {
            const int kb = c << 6;
            const bool fromAct = (s > 0) && (kb < 128);

            // W chunk via cp.async (issued first; overlaps A staging / math below)
            for (int idx = tid; idx < 1024; idx += 256) {
                int n = idx >> 3, seg = idx & 7;
                size_t go = (size_t)n * Kp + kb + seg * 8;
                uint32_t so = n * CH_STR + seg * 8;
                cp16(smem_u32(CHW_H + so), WH + go);
                cp16(smem_u32(CHW_L + so), WL + go);
            }
            asm volatile("cp.async.commit_group;" ::: "memory");

            if (!fromAct) {
                // A chunk: 64 rows x 32 col-pairs
                for (int idx = tid; idx < 2048; idx += 256) {
                    int r = idx >> 5, clp = idx & 31;
                    int gk = kb + (clp << 1);
                    float v0 = 0.f, v1 = 0.f;
                    if (s == 0) {
                        if (gk < 128) {
                            float2 t = *(const float2*)(memory + (size_t)ida_s[r] * 128 + gk);
                            v0 = t.x; v1 = t.y;
                        } else if (gk < 256) {
                            float2 t = *(const float2*)(memory + (size_t)idb_s[r] * 128 + (gk - 128));
                            v0 = t.x; v1 = t.y;
                        } else if (gk < 384) {
                            float2 t = *(const float2*)(edge + (size_t)(brow + r) * 128 + (gk - 256));
                            v0 = t.x; v1 = t.y;
                        } else if (gk < 484) {
                            int t0 = gk - 384;
                            v0 = cosf(ts_s[r] * tw_s[t0] + tb_s[t0]);
                            if (t0 + 1 < TIMED) v1 = cosf(ts_s[r] * tw_s[t0 + 1] + tb_s[t0 + 1]);
                        }
                    } else if (s == 4) {
                        int t0 = gk - 128;
                        if (t0 < TIMED)     v0 = cosf(ts_s[r] * tw_s[t0] + tb_s[t0]);
                        if (t0 + 1 < TIMED) v1 = cosf(ts_s[r] * tw_s[t0 + 1] + tb_s[t0 + 1]);
                    } else { // s == 5
                        int e0 = gk - 128;
                        if (e0 < 128) {
                            float2 t = *(const float2*)(P.emb + (size_t)(brow + r) * 128 + e0);
                            v0 = t.x; v1 = t.y;
                        }
                    }
                    uint32_t hi, lo; split2(v0, v1, hi, lo);
                    *(uint32_t*)(CHA_H + r * CH_STR + (clp << 1)) = hi;
                    *(uint32_t*)(CHA_L + r * CH_STR + (clp << 1)) = lo;
                }
            }
            asm volatile("cp.async.wait_group 0;" ::: "memory");
            __syncthreads();

            const __nv_bfloat16* AbH = fromAct ? ACT_H : CHA_H;
            const __nv_bfloat16* AbL = fromAct ? ACT_L : CHA_L;
            const int astr = fromAct ? ACT_STR : CH_STR;
            const int acol = fromAct ? kb : 0;

            #pragma unroll
            for (int kk = 0; kk < 64; kk += 16) {
                uint32_t ah[4], al[4], bh[8][2], bl[8][2];
                ldm_x4(ah, smem_u32(AbH + (wm + arow) * astr + acol + kk + akoff));
                ldm_x4(al, smem_u32(AbL + (wm + arow) * astr + acol + kk + akoff));
                #pragma unroll
                for (int nb = 0; nb < 4; nb++) {
                    uint32_t r4[4];
                    ldm_x4(r4, smem_u32(CHW_H + (wn + nb * 16 + brw2) * CH_STR + kk + bkoff));
                    bh[nb * 2][0] = r4[0]; bh[nb * 2][1] = r4[1];
                    bh[nb * 2 + 1][0] = r4[2]; bh[nb * 2 + 1][1] = r4[3];
                    ldm_x4(r4, smem_u32(CHW_L + (wn + nb * 16 + brw2) * CH_STR + kk + bkoff));
                    bl[nb * 2][0] = r4[0]; bl[nb * 2][1] = r4[1];
                    bl[nb * 2 + 1][0] = r4[2]; bl[nb * 2 + 1][1] = r4[3];
                }
                #pragma unroll
                for (int ni = 0; ni < 8; ni++) {
                    mma_bf16(acc[ni], ah, bh[ni]);
                    mma_bf16(acc[ni], ah, bl[ni]);
                    mma_bf16(acc[ni], al, bh[ni]);
                }
            }
            __syncthreads();
        }

        const float* bias = P.bias[s];
        #pragma unroll
        for (int ni = 0; ni < 8; ni++) {
            int col = wn + ni * 8 + q * 2;
            float bv0 = bias[col], bv1 = bias[col + 1];
            #pragma unroll
            for (int h = 0; h < 2; h++) {
                int row = wm + g + h * 8;
                float v0 = acc[ni][h * 2] + bv0;
                float v1 = acc[ni][h * 2 + 1] + bv1;
                if (rl[s]) { v0 = fmaxf(v0, 0.f); v1 = fmaxf(v1, 0.f); }
                if (s < 5) {
                    uint32_t hi, lo; split2(v0, v1, hi, lo);
                    *(uint32_t*)(ACT_H + row * ACT_STR + col) = hi;
                    *(uint32_t*)(ACT_L + row * ACT_STR + col) = lo;
                    if (s == 4)
                        *(float2*)(P.ut + (size_t)(brow + row) * 128 + col) = make_float2(v0, v1);
                } else {
                    *(float2*)(P.outp + (size_t)(brow + row) * 128 + col) = make_float2(v0, v1);
                }
            }
        }
        __syncthreads();
    }
}

// ---------------- winner + memory output ----------------
__global__ void win_init_kernel(int nodes)
{
    int i = blockIdx.x * blockDim.x + threadIdx.x;
    if (i < nodes) g_win[i] = -1;
}
__global__ void win_mark_kernel(const int* __restrict__ src, const int* __restrict__ dst, int Bn)
{
    int i = blockIdx.x * blockDim.x + threadIdx.x;
    if (i < 2 * Bn) {
        int id = (i < Bn) ? src[i] : dst[i - Bn];
        atomicMax(&g_win[id], i);
    }
}
__global__ void copy_pass_kernel(const float4* __restrict__ mem4,
                                 float4* __restrict__ out4, int nodes)
{
    size_t idx = (size_t)blockIdx.x * blockDim.x + threadIdx.x;
    if (idx >= (size_t)nodes * 32) return;
    int row = (int)(idx >> 5);
    if (g_win[row] >= 0) return;
    out4[idx] = mem4[idx];
}
__global__ void scatter_win_kernel(const int* __restrict__ src, const int* __restrict__ dst,
                                   const float* __restrict__ ut, const float* __restrict__ it,
                                   float* __restrict__ out_mem, int Bn)
{
    int i = blockIdx.x;
    int j = threadIdx.x;
    int id;
    const float* row;
    if (i < Bn) { id = src[i];      row = ut + (size_t)i * 128; }
    else        { id = dst[i - Bn]; row = it + (size_t)(i - Bn) * 128; }
    if (g_win[id] == i)
        out_mem[(size_t)id * 128 + j] = row[j];
}

// ---------------- launch ----------------
extern "C" void kernel_launch(void* const* d_in, const int* in_sizes, int n_in,
                              void* d_out, int out_size)
{
    const float* src_emb = (const float*)d_in[0];
    const float* dst_emb = (const float*)d_in[1];
    const int*   src_ids = (const int*)  d_in[2];
    const int*   dst_ids = (const int*)  d_in[3];
    const float* edge    = (const float*)d_in[4];
    const float* ts      = (const float*)d_in[5];
    const float* memory  = (const float*)d_in[6];
    const float* tw      = (const float*)d_in[7];
    const float* tb      = (const float*)d_in[8];
    const float* Wu1 = (const float*)d_in[9];   const float* bu1 = (const float*)d_in[10];
    const float* Wu2 = (const float*)d_in[11];  const float* bu2 = (const float*)d_in[12];
    const float* Wi1 = (const float*)d_in[13];  const float* bi1 = (const float*)d_in[14];
    const float* Wi2 = (const float*)d_in[15];  const float* bi2 = (const float*)d_in[16];
    const float* Wp1 = (const float*)d_in[17];  const float* bp1 = (const float*)d_in[18];
    const float* Wp2 = (const float*)d_in[19];  const float* bp2 = (const float*)d_in[20];
    const float* Wt1 = (const float*)d_in[21];  const float* bt1 = (const float*)d_in[22];
    const float* Wo  = (const float*)d_in[23];  const float* bo  = (const float*)d_in[24];

    const int Bn    = in_sizes[5];
    const int nodes = in_sizes[6] / MEMD;
    float* out = (float*)d_out;

    float *ut, *it;
    cudaGetSymbolAddress((void**)&ut, g_ut);
    cudaGetSymbolAddress((void**)&it, g_it);

    const int SMEM_DYN = SMEM_ELE * (int)sizeof(__nv_bfloat16);  // ~90KB
    cudaFuncSetAttribute(chain_kernel, cudaFuncAttributeMaxDynamicSharedMemorySize, SMEM_DYN);

    static cudaStream_t s2 = nullptr;
    static cudaEvent_t evFork = nullptr, evMark = nullptr, evCopy = nullptr;
    if (!s2) {
        cudaStreamCreateWithFlags(&s2, cudaStreamNonBlocking);
        cudaEventCreateWithFlags(&evFork, cudaEventDisableTiming);
        cudaEventCreateWithFlags(&evMark, cudaEventDisableTiming);
        cudaEventCreateWithFlags(&evCopy, cudaEventDisableTiming);
    }

    long outHead = (long)2 * Bn * MEMD;
    bool hasMem = ((long)out_size >= outHead + (long)nodes * MEMD);
    float* out_mem = out + outHead;

    // ---- fork side stream: winner calc + bulk copy, concurrent with chain ----
    cudaEventRecord(evFork, 0);
    cudaStreamWaitEvent(s2, evFork, 0);
    win_init_kernel<<<(nodes + 255) / 256, 256, 0, s2>>>(nodes);
    win_mark_kernel<<<(2 * Bn + 255) / 256, 256, 0, s2>>>(src_ids, dst_ids, Bn);
    cudaEventRecord(evMark, s2);
    if (hasMem) {
        size_t total = (size_t)nodes * 32;
        copy_pass_kernel<<<(unsigned)((total + 255) / 256), 256, 0, s2>>>(
            (const float4*)memory, (float4*)out_mem, nodes);
    }
    cudaEventRecord(evCopy, s2);

    // ---- main stream: fused weight prep (1 launch) + fused chain ----
    PrepArgs pa;
    const float* Ws[8] = {Wu1, Wi1, Wu2, Wi2, Wp1, Wp2, Wt1, Wo};
    int Ks[8]  = {484, 484, 128, 128, 128, 128, 228, 256};
    int Kps[8] = {512, 512, 128, 128, 128, 128, 256, 256};
    int Bs[8]  = {PB_U1, PB_I1, PB_U2, PB_I2, PB_P1, PB_P2, PB_T1, PB_O};
    int cum = 0;
    for (int i = 0; i < 8; i++) {
        pa.W[i] = Ws[i]; pa.K[i] = Ks[i]; pa.Kp[i] = Kps[i]; pa.base[i] = Bs[i];
        pa.cum[i] = cum; cum += Kps[i];
    }
    pa.cum[8] = cum;
    prep_all_kernel<<<cum, 128>>>(pa);

    ChainArgs U, I;
    U.ida = src_ids; U.idb = dst_ids; U.emb = src_emb;
    int ubase[6] = {PB_U1, PB_U2, PB_P1, PB_P2, PB_T1, PB_O};
    int ibase[6] = {PB_I1, PB_I2, PB_P1, PB_P2, PB_T1, PB_O};
    int kps6[6]  = {512, 128, 128, 128, 256, 256};
    for (int s = 0; s < 6; s++) { U.wbase[s] = ubase[s]; I.wbase[s] = ibase[s]; U.kp[s] = I.kp[s] = kps6[s]; }
    U.bias[0] = bu1; U.bias[1] = bu2; U.bias[2] = bp1; U.bias[3] = bp2; U.bias[4] = bt1; U.bias[5] = bo;
    I.bias[0] = bi1; I.bias[1] = bi2; I.bias[2] = bp1; I.bias[3] = bp2; I.bias[4] = bt1; I.bias[5] = bo;
    U.ut = ut; U.outp = out;
    I.ida = dst_ids; I.idb = src_ids; I.emb = dst_emb;
    I.ut = it; I.outp = out + (size_t)Bn * MEMD;

    dim3 grid(Bn / MROWS, 2);
    chain_kernel<<<grid, 256, SMEM_DYN>>>(U, I, memory, edge, ts, tw, tb);

    // ---- join ----
    if (hasMem) {
        cudaStreamWaitEvent(0, evMark, 0);
        scatter_win_kernel<<<2 * Bn, 128>>>(src_ids, dst_ids, ut, it, out_mem, Bn);
    }
    cudaStreamWaitEvent(0, evCopy, 0);
}